// round 17
// baseline (speedup 1.0000x reference)
#include <cuda_runtime.h>

#define BATCH 8
#define INPUT_SIZE 8192
#define HIDDEN_SIZE 8192
#define OUTPUT_SIZE 2048
#define KDIM 16384

typedef unsigned long long u64;

// ---- Kernel 1: 8 K-slices x 37 persistent blocks = 296 -------------------
#define NSLICE1 8
#define KSLICE1 (KDIM / NSLICE1)        // 2048
#define KS1_16B (KSLICE1 / 4)           // 512 x 16B per batch
#define BLKS_PER_SLICE1 37
#define R1 4
#define TILE_ROWS_1 (R1 * 8)            // 32
#define NTILES1 (HIDDEN_SIZE / TILE_ROWS_1)   // 256

// ---- Kernel 2: 64 row tiles x 4 K-splits = 256 blocks ---------------------
#define R2 4
#define TILE_ROWS_2 (R2 * 8)            // 32
#define NTILES2 (OUTPUT_SIZE / TILE_ROWS_2)   // 64
#define NSPLIT2 4
#define KQ (HIDDEN_SIZE / NSPLIT2)      // 2048
#define TK  1024
#define TK16 (TK / 4)                   // 256 x 16B per batch per chunk

// Scratch (allocation-free)
__device__ float g_p1[NSLICE1][BATCH][HIDDEN_SIZE];   // 2 MB
__device__ float g_hidden[BATCH * HIDDEN_SIZE];       // 256 KB
__device__ float g_p2[NSPLIT2][BATCH][OUTPUT_SIZE];   // 256 KB

// Monotonic per-tile arrival counters (no reset needed: old % N == N-1
// identifies the last arrival of THIS replay deterministically).
__device__ unsigned g_cnt1[NTILES1];
__device__ unsigned g_cnt2[NTILES2];

// ---------------------------------------------------------------------------
__device__ __forceinline__ void cp_async16(void* smem_dst, const void* gmem_src) {
    unsigned s = (unsigned)__cvta_generic_to_shared(smem_dst);
    asm volatile("cp.async.cg.shared.global [%0], [%1], 16;\n" :: "r"(s), "l"(gmem_src));
}
__device__ __forceinline__ void cp_commit()  { asm volatile("cp.async.commit_group;\n"); }
__device__ __forceinline__ void cp_wait1()   { asm volatile("cp.async.wait_group 1;\n"); }
__device__ __forceinline__ void cp_wait0()   { asm volatile("cp.async.wait_group 0;\n"); }

// Packed dual-FMA (non-volatile, reorderable); operands are native
// ulonglong2 halves from LDG.128/LDS.128 — zero packing cost.
__device__ __forceinline__ void fma2(u64& d, u64 a, u64 b) {
    asm("fma.rn.f32x2 %0, %1, %2, %0;" : "+l"(d) : "l"(a), "l"(b));
}
__device__ __forceinline__ float pair_sum(u64 v) {
    return __uint_as_float((unsigned)v) + __uint_as_float((unsigned)(v >> 32));
}

// ===========================================================================
// Kernel 1: persistent slice-resident i2h partial GEMV (FFMA2) with
// last-arriver tanh reduction — the 8th block (one per slice) to finish a
// row tile sums the 8 partials + bias and writes g_hidden. No reduce launch.
// ===========================================================================
__global__ __launch_bounds__(256, 2)
void rnn_i2h_kernel(const float* __restrict__ x,
                    const float* __restrict__ h0,
                    const float* __restrict__ W,      // [HIDDEN, KDIM]
                    const float* __restrict__ bias1)
{
    extern __shared__ ulonglong2 s_in[];              // [BATCH][KS1_16B] 64 KB
    __shared__ int s_last;

    const int tid   = threadIdx.x;
    const int lane  = tid & 31;
    const int warp  = tid >> 5;
    const int slice = blockIdx.x / BLKS_PER_SLICE1;   // 0..7
    const int local = blockIdx.x % BLKS_PER_SLICE1;   // 0..36

    const float* in = (slice < NSLICE1 / 2)
                        ? (x  + slice * KSLICE1)
                        : (h0 + slice * KSLICE1 - INPUT_SIZE);
    #pragma unroll
    for (int t = 0; t < 16; ++t) {
        int f  = tid + t * 256;
        int b  = f >> 9;                   // / KS1_16B
        int k4 = f & (KS1_16B - 1);
        s_in[b * KS1_16B + k4] =
            ((const ulonglong2*)(in + (size_t)b * INPUT_SIZE))[k4];
    }
    __syncthreads();

    const size_t koff = (size_t)slice * KSLICE1;

    for (int tile = local; tile < NTILES1; tile += BLKS_PER_SLICE1) {
        const int row0 = tile * TILE_ROWS_1 + warp * R1;

        u64 acc[R1][BATCH];
        #pragma unroll
        for (int r = 0; r < R1; r++)
            #pragma unroll
            for (int b = 0; b < BATCH; b++)
                acc[r][b] = 0ull;

        const ulonglong2* Wc0 = (const ulonglong2*)(W + (size_t)(row0 + 0) * KDIM + koff);
        const ulonglong2* Wc1 = (const ulonglong2*)(W + (size_t)(row0 + 1) * KDIM + koff);
        const ulonglong2* Wc2 = (const ulonglong2*)(W + (size_t)(row0 + 2) * KDIM + koff);
        const ulonglong2* Wc3 = (const ulonglong2*)(W + (size_t)(row0 + 3) * KDIM + koff);

        #pragma unroll
        for (int i = 0; i < KS1_16B / 32; ++i) {      // 16 strips
            const int k4 = i * 32 + lane;
            ulonglong2 w0 = __ldcs(Wc0 + k4);
            ulonglong2 w1 = __ldcs(Wc1 + k4);
            ulonglong2 w2 = __ldcs(Wc2 + k4);
            ulonglong2 w3 = __ldcs(Wc3 + k4);

            #pragma unroll
            for (int b = 0; b < BATCH; b++) {
                ulonglong2 v = s_in[b * KS1_16B + k4];
                fma2(acc[0][b], w0.x, v.x);
                fma2(acc[0][b], w0.y, v.y);
                fma2(acc[1][b], w1.x, v.x);
                fma2(acc[1][b], w1.y, v.y);
                fma2(acc[2][b], w2.x, v.x);
                fma2(acc[2][b], w2.y, v.y);
                fma2(acc[3][b], w3.x, v.x);
                fma2(acc[3][b], w3.y, v.y);
            }
        }

        #pragma unroll
        for (int r = 0; r < R1; r++) {
            #pragma unroll
            for (int b = 0; b < BATCH; b++) {
                float s = pair_sum(acc[r][b]);
                #pragma unroll
                for (int off = 16; off > 0; off >>= 1)
                    s += __shfl_xor_sync(0xffffffffu, s, off);
                if (lane == b)
                    g_p1[slice][b][row0 + r] = s;
            }
        }

        // ---- last-arriver tanh reduction for this tile --------------------
        __syncthreads();                       // all warps' partials issued
        if (tid == 0) {
            __threadfence();                   // publish partials
            unsigned old = atomicAdd(&g_cnt1[tile], 1u);
            s_last = ((old & (NSLICE1 - 1)) == NSLICE1 - 1);
        }
        __syncthreads();
        if (s_last) {
            __threadfence();                   // acquire others' partials
            // 256 threads -> 32 rows x 8 batches
            const int rr = tid >> 3;           // 0..31
            const int b  = tid & 7;
            const int row = tile * TILE_ROWS_1 + rr;
            float s = __ldg(bias1 + row);
            #pragma unroll
            for (int sl = 0; sl < NSLICE1; sl++)
                s += g_p1[sl][b][row];
            g_hidden[b * HIDDEN_SIZE + row] = tanhf(s);
        }
    }
}

// ===========================================================================
// Kernel 2: h2o partial GEMV (4 rows/warp, K-split x4, FFMA2) with
// last-arriver final reduction — the 4th split block for a tile sums the 4
// partials + bias2 and writes out. No reduce launch.
// ===========================================================================
__global__ __launch_bounds__(256, 2)
void rnn_h2o_kernel(const float* __restrict__ W2,     // [OUT, HIDDEN]
                    const float* __restrict__ bias2,
                    float* __restrict__ out)
{
    __shared__ ulonglong2 s_in[2][BATCH][TK16];   // 2 x 32 KB
    __shared__ int s_last;

    const int tid   = threadIdx.x;
    const int lane  = tid & 31;
    const int warp  = tid >> 5;
    const int tile  = blockIdx.x & (NTILES2 - 1);   // 0..63
    const int split = blockIdx.x >> 6;              // 0..3
    const int row0  = tile * TILE_ROWS_2 + warp * R2;
    const int kbase = split * KQ;

    const int NCHUNK = KQ / TK;   // 2

    u64 acc[R2][BATCH];
    #pragma unroll
    for (int r = 0; r < R2; r++)
        #pragma unroll
        for (int b = 0; b < BATCH; b++)
            acc[r][b] = 0ull;

    auto stage = [&](int c, int buf) {
        const float* src = g_hidden + kbase + c * TK;
        #pragma unroll
        for (int t = 0; t < 8; ++t) {
            int f  = tid + t * 256;
            int b  = f >> 8;               // / TK16
            int k4 = f & (TK16 - 1);
            cp_async16(&s_in[buf][b][k4],
                       (const float4*)(src + (size_t)b * HIDDEN_SIZE) + k4);
        }
        cp_commit();
    };

    stage(0, 0);

    const ulonglong2* W0 = (const ulonglong2*)(W2 + (size_t)(row0 + 0) * HIDDEN_SIZE + kbase);
    const ulonglong2* W1 = (const ulonglong2*)(W2 + (size_t)(row0 + 1) * HIDDEN_SIZE + kbase);
    const ulonglong2* Wv = (const ulonglong2*)(W2 + (size_t)(row0 + 2) * HIDDEN_SIZE + kbase);
    const ulonglong2* W3 = (const ulonglong2*)(W2 + (size_t)(row0 + 3) * HIDDEN_SIZE + kbase);

    for (int c = 0; c < NCHUNK; ++c) {
        const int buf = c & 1;
        __syncthreads();
        if (c + 1 < NCHUNK) { stage(c + 1, buf ^ 1); cp_wait1(); }
        else                { cp_wait0(); }
        __syncthreads();

        const ulonglong2* Wc0 = W0 + c * TK16;
        const ulonglong2* Wc1 = W1 + c * TK16;
        const ulonglong2* Wc2 = Wv + c * TK16;
        const ulonglong2* Wc3 = W3 + c * TK16;

        #pragma unroll
        for (int i = 0; i < TK16 / 32; ++i) {         // 8 strips
            const int k4 = i * 32 + lane;
            ulonglong2 w0 = __ldcs(Wc0 + k4);
            ulonglong2 w1 = __ldcs(Wc1 + k4);
            ulonglong2 w2 = __ldcs(Wc2 + k4);
            ulonglong2 w3 = __ldcs(Wc3 + k4);

            #pragma unroll
            for (int b = 0; b < BATCH; b++) {
                ulonglong2 v = s_in[buf][b][k4];
                fma2(acc[0][b], w0.x, v.x);
                fma2(acc[0][b], w0.y, v.y);
                fma2(acc[1][b], w1.x, v.x);
                fma2(acc[1][b], w1.y, v.y);
                fma2(acc[2][b], w2.x, v.x);
                fma2(acc[2][b], w2.y, v.y);
                fma2(acc[3][b], w3.x, v.x);
                fma2(acc[3][b], w3.y, v.y);
            }
        }
    }

    #pragma unroll
    for (int r = 0; r < R2; r++) {
        #pragma unroll
        for (int b = 0; b < BATCH; b++) {
            float s = pair_sum(acc[r][b]);
            #pragma unroll
            for (int off = 16; off > 0; off >>= 1)
                s += __shfl_xor_sync(0xffffffffu, s, off);
            if (lane == b)
                g_p2[split][b][row0 + r] = s;
        }
    }

    // ---- last-arriver final reduction for this tile -----------------------
    __syncthreads();
    if (tid == 0) {
        __threadfence();
        unsigned old = atomicAdd(&g_cnt2[tile], 1u);
        s_last = ((old & (NSPLIT2 - 1)) == NSPLIT2 - 1);
    }
    __syncthreads();
    if (s_last) {
        __threadfence();
        // 256 threads -> 32 rows x 8 batches
        const int rr = tid >> 3;
        const int b  = tid & 7;
        const int row = tile * TILE_ROWS_2 + rr;
        float s = __ldg(bias2 + row);
        #pragma unroll
        for (int sp = 0; sp < NSPLIT2; sp++)
            s += g_p2[sp][b][row];
        out[b * OUTPUT_SIZE + row] = s;
    }
}

// ---------------------------------------------------------------------------
// Inputs: x, initial_hidden, i2h_weight, i2h_bias, h2o_weight, h2o_bias
// ---------------------------------------------------------------------------
extern "C" void kernel_launch(void* const* d_in, const int* in_sizes, int n_in,
                              void* d_out, int out_size) {
    const float* x  = (const float*)d_in[0];
    const float* h0 = (const float*)d_in[1];
    const float* W1 = (const float*)d_in[2];
    const float* b1 = (const float*)d_in[3];
    const float* W2 = (const float*)d_in[4];
    const float* b2 = (const float*)d_in[5];
    float* out      = (float*)d_out;

    const int SMEM1 = BATCH * KS1_16B * sizeof(ulonglong2);   // 64 KB dynamic
    cudaFuncSetAttribute(rnn_i2h_kernel,
                         cudaFuncAttributeMaxDynamicSharedMemorySize, SMEM1);

    rnn_i2h_kernel<<<NSLICE1 * BLKS_PER_SLICE1, 256, SMEM1>>>(x, h0, W1, b1);
    rnn_h2o_kernel<<<NTILES2 * NSPLIT2, 256>>>(W2, b2, out);
}